// round 16
// baseline (speedup 1.0000x reference)
#include <cuda_runtime.h>
#include <cuda_fp16.h>
#include <cstdint>
#include <cstring>

// Problem constants
#define BATCH_SEQ 640          // B*S = 32*20
#define THREADS   256
#define ADJ_THR   0.05f
#define FULLC     456          // full-CTA count (= 152 SMs x 3 CTAs)
#define TAILB     (BATCH_SEQ - FULLC)   // 184 tail batch-seqs, 2 CTAs each

__device__ __forceinline__ float rcp_approx(float x) {
    float r; asm("rcp.approx.f32 %0, %1;" : "=f"(r) : "f"(x)); return r;
}
__device__ __forceinline__ uint32_t h2u(half2 v) { uint32_t r; memcpy(&r, &v, 4); return r; }
__device__ __forceinline__ half2 u2h(uint32_t v) { half2 r; memcpy(&r, &v, 4); return r; }
// exp(sigmoid(x)) pairwise in fp16: 2^(c*tanh(x/2)+c), c = log2(e)/2
#define EXP_SIG_C 0.72134752044f
// fp16 mma m16n8k16, fp32 accum
__device__ __forceinline__ void mma_f16(float c[4],
                                        uint32_t a0, uint32_t a1, uint32_t a2, uint32_t a3,
                                        uint32_t b0, uint32_t b1) {
    asm volatile("mma.sync.aligned.m16n8k16.row.col.f32.f16.f16.f32 "
                 "{%0,%1,%2,%3}, {%4,%5,%6,%7}, {%8,%9}, {%0,%1,%2,%3};"
                 : "+f"(c[0]), "+f"(c[1]), "+f"(c[2]), "+f"(c[3])
                 : "r"(a0), "r"(a1), "r"(a2), "r"(a3), "r"(b0), "r"(b1));
}
__device__ __forceinline__ uint32_t cvta_s(const void* p) {
    uint32_t a; asm("{ .reg .u64 t; cvta.to.shared.u64 t, %1; cvt.u32.u64 %0, t; }"
                    : "=r"(a) : "l"(p));
    return a;
}
__device__ __forceinline__ void ldm_x4(uint32_t& r0, uint32_t& r1,
                                       uint32_t& r2, uint32_t& r3, uint32_t a) {
    asm volatile("ldmatrix.sync.aligned.m8n8.x4.shared.b16 {%0,%1,%2,%3}, [%4];"
                 : "=r"(r0), "=r"(r1), "=r"(r2), "=r"(r3) : "r"(a));
}
__device__ __forceinline__ void ldm_x4_t(uint32_t& r0, uint32_t& r1,
                                         uint32_t& r2, uint32_t& r3, uint32_t a) {
    asm volatile("ldmatrix.sync.aligned.m8n8.x4.trans.shared.b16 {%0,%1,%2,%3}, [%4];"
                 : "=r"(r0), "=r"(r1), "=r"(r2), "=r"(r3) : "r"(a));
}
__device__ __forceinline__ void red_add_f32(float* p, float v) {
    asm volatile("red.global.add.f32 [%0], %1;" :: "l"(p), "f"(v) : "memory");
}

// Shared memory layout (bytes) — ONE head resident at a time:
//   hs   [128 row][64 k] fp16 XOR-swz @ 0      (16384)
//   htt  [64 o][136 k-halves] fp16    @ 16384  (17408)  current head's ht^T
//   ATT  @ 33792 (34816):
//     GEMM1 phase: Wtk [64 k][64 o] fp16, o XOR-swz by k  (8192)
//     attn phase : attn [128 i][136 k] fp16
//   src_s [128] f32  @ 68608 (512)
//   tgt_s [128] f32  @ 69120 (512)
//   maskb [512] u32  @ 69632 (2048)
//   a_s   [512] f32  @ 71680 (2048)
// total 73728 B -> 3 CTAs/SM
#define HTS       136
#define HTT_OFF   16384
#define ATT_OFF   33792
#define SRC_OFF   68608
#define TGT_OFF   69120
#define MSK_OFF   69632
#define AS_OFF    71680
#define SMEM_BYTES 73728

extern __shared__ char smem_b[];

__global__ __launch_bounds__(THREADS, 3)
void gat_fused_kernel(const float* __restrict__ hg,
                      const float* __restrict__ adjg,
                      const float* __restrict__ Wg,
                      const float* __restrict__ ag,
                      float* __restrict__ outg)
{
    __half* hs     = (__half*)smem_b;
    __half* htt    = (__half*)(smem_b + HTT_OFF);
    __half* attn_h = (__half*)(smem_b + ATT_OFF);
    __half* Wtk    = (__half*)(smem_b + ATT_OFF);   // union with attn
    float*  src_s  = (float*)(smem_b + SRC_OFF);
    float*  tgt_s  = (float*)(smem_b + TGT_OFF);
    unsigned* maskb = (unsigned*)(smem_b + MSK_OFF);
    float*  a_s    = (float*)(smem_b + AS_OFF);

    const int tid  = threadIdx.x;
    const int lane = tid & 31;
    const int wid  = tid >> 5;      // 0..7
    const int g    = lane >> 2;     // 0..7
    const int t    = lane & 3;      // 0..3
    const int lrow = lane & 15;
    const int lhi  = lane >> 4;
    const int bid  = blockIdx.x;

    // ---- Mixed-grid decode: full CTA (4 heads) or tail CTA (head pair) ----
    int bs, h0, h1;
    bool full;
    if (bid < FULLC) {
        bs = bid; h0 = 0; h1 = 4; full = true;
    } else {
        int r  = bid - FULLC;
        bs = FULLC + (r >> 1);
        h0 = (r & 1) * 2; h1 = h0 + 2; full = false;
    }
    float* obase = outg + (size_t)bs * 128 * 64;

    const float* hb   = hg   + (size_t)bs * 128 * 64;
    const float* adjb = adjg + (size_t)bs * 128 * 128;

    const uint32_t hs_s  = cvta_s(hs);
    const uint32_t htt_s = cvta_s(htt);
    const uint32_t att_s = cvta_s(attn_h);
    const uint32_t wtk_s = att_s;

    // ---------------- Prologue: a_s, adjacency bitmask, hs (fp16 h) -----------
    a_s[tid]       = ag[tid];
    a_s[256 + tid] = ag[256 + tid];

    // adj mask via float4 + nibble shfl-OR tree (same word layout as ballot:
    // bit j%32 of word row*4 + j/32). Each warp does one row per iteration;
    // lane L covers j = 4L..4L+3 -> nibble at bit 4*(L&7) of word L>>3.
    {
        const int nsh = 4 * (lane & 7);
        #pragma unroll 4
        for (int it = 0; it < 16; it++) {
            const int row = it * 8 + wid;
            float4 v = *(const float4*)&adjb[row * 128 + 4 * lane];
            unsigned nib = (v.x < ADJ_THR ? 1u : 0u) | (v.y < ADJ_THR ? 2u : 0u)
                         | (v.z < ADJ_THR ? 4u : 0u) | (v.w < ADJ_THR ? 8u : 0u);
            unsigned word = nib << nsh;
            word |= __shfl_xor_sync(0xffffffffu, word, 1);
            word |= __shfl_xor_sync(0xffffffffu, word, 2);
            word |= __shfl_xor_sync(0xffffffffu, word, 4);
            if ((lane & 7) == 0) maskb[row * 4 + (lane >> 3)] = word;
        }
    }

    // hs[row][k ^ 8*(row&7)] fp16
    #pragma unroll
    for (int it = 0; it < 8; it++) {
        int idx = it * 256 + tid;
        int row = idx >> 4;
        int k4  = (idx & 15) * 4;
        float4 v = *(const float4*)&hb[row * 64 + k4];
        __half* p = hs + row * 64 + (k4 ^ (8 * (row & 7)));
        *(half2*)p       = __floats2half2_rn(v.x, v.y);
        *(half2*)(p + 2) = __floats2half2_rn(v.z, v.w);
    }

    // GEMM2 accumulator: warp tile 32 rows x 32 cols, full K, heads h0..h1
    const int rblk = wid >> 1;      // row block (32 rows)
    const int chf  = wid & 1;       // col half (32 cols)
    float C[8][4];
    #pragma unroll
    for (int i = 0; i < 8; i++)
        #pragma unroll
        for (int q = 0; q < 4; q++) C[i][q] = 0.f;

    // ================== Per-head pipeline ==================
    #pragma unroll 1
    for (int h = h0; h < h1; h++) {
        __syncthreads();   // prev GEMM2 attn reads done (or prologue hs done)

        // ---- Stage Wtk[k][o ^ 8*(k&7)] = W[k][h*64+o] fp16 ----
        #pragma unroll
        for (int it = 0; it < 4; it++) {
            int idx = it * 256 + tid;
            int k   = idx >> 4;
            int o4  = (idx & 15) * 4;
            float4 v = *(const float4*)&Wg[k * 256 + h * 64 + o4];
            int base = k * 64 + (o4 ^ (8 * (k & 7)));
            *(half2*)&Wtk[base]     = __floats2half2_rn(v.x, v.y);
            *(half2*)&Wtk[base + 2] = __floats2half2_rn(v.z, v.w);
        }
        __syncthreads();

        // ---- GEMM1: htt[o][row] = W_h^T @ h^T ; warp tile 16 o x 64 rows ----
        {
            const int ob = (wid >> 1) * 16;   // o block
            const int rb = wid & 1;           // row half (64 rows)
            const int krow = (lane & 7) + 8 * lhi;            // 0..15
            const int och  = ob + 8 * ((lane >> 3) & 1);
            const uint32_t aA_base =
                wtk_s + 2 * (krow * 64 + (och ^ (8 * (krow & 7))));
            const uint32_t aB0 = hs_s + 2 * ((rb * 64 + lrow) * 64);

            #pragma unroll
            for (int qh = 0; qh < 2; qh++) {
                float D[4][4];
                #pragma unroll
                for (int i = 0; i < 4; i++)
                    #pragma unroll
                    for (int q = 0; q < 4; q++) D[i][q] = 0.f;

                #pragma unroll
                for (int ks = 0; ks < 4; ks++) {
                    uint32_t A0, A1, A2, A3;
                    ldm_x4_t(A0, A1, A2, A3, aA_base + ks * 2048);
                    const int chunk = ((ks * 16 + 8 * lhi) ^ (8 * (lrow & 7))) * 2;
                    #pragma unroll
                    for (int q2 = 0; q2 < 2; q2++) {
                        const int q = qh * 2 + q2;
                        uint32_t r0, r1, r2, r3;
                        ldm_x4(r0, r1, r2, r3, aB0 + 2 * (q * 16 * 64) + chunk);
                        mma_f16(D[2 * q2],     A0, A1, A2, A3, r0, r2);
                        mma_f16(D[2 * q2 + 1], A0, A1, A2, A3, r1, r3);
                    }
                }
                // store htt (half2, conflict-free)
                #pragma unroll
                for (int q2 = 0; q2 < 2; q2++) {
                    #pragma unroll
                    for (int j = 0; j < 2; j++) {
                        const float* c = D[2 * q2 + j];
                        const int row = rb * 64 + (qh * 2 + q2) * 16 + j * 8 + 2 * t;
                        *(half2*)&htt[(ob + g) * HTS + row] =
                            __floats2half2_rn(c[0], c[1]);
                        *(half2*)&htt[(ob + g + 8) * HTS + row] =
                            __floats2half2_rn(c[2], c[3]);
                    }
                }
            }
        }
        __syncthreads();   // htt visible

        // ---- src/tgt: exact fp32 dots over htt columns (conflict-free) ----
        {
            const int ol = lane & 7;
            const int rp = lane >> 3;
            #pragma unroll
            for (int pass = 0; pass < 2; pass++) {
                const int row = wid * 16 + 2 * (rp + 4 * pass);
                float s0 = 0.f, s1 = 0.f, t0 = 0.f, t1 = 0.f;
                #pragma unroll
                for (int oo = 0; oo < 8; oo++) {
                    const int o = oo * 8 + ol;
                    float2 f = __half22float2(*(const half2*)&htt[o * HTS + row]);
                    float av = a_s[h * 128 + o];
                    float bv = a_s[h * 128 + 64 + o];
                    s0 = fmaf(f.x, av, s0); s1 = fmaf(f.y, av, s1);
                    t0 = fmaf(f.x, bv, t0); t1 = fmaf(f.y, bv, t1);
                }
                #pragma unroll
                for (int m = 1; m <= 4; m <<= 1) {
                    s0 += __shfl_xor_sync(0xffffffffu, s0, m);
                    s1 += __shfl_xor_sync(0xffffffffu, s1, m);
                    t0 += __shfl_xor_sync(0xffffffffu, t0, m);
                    t1 += __shfl_xor_sync(0xffffffffu, t1, m);
                }
                if (ol == 0) {
                    float2 sv; sv.x = s0; sv.y = s1;
                    float2 tv; tv.x = t0; tv.y = t1;
                    *(float2*)&src_s[row] = sv;
                    *(float2*)&tgt_s[row] = tv;
                }
            }
        }
        __syncthreads();   // src/tgt ready; Wtk dead -> attn region free

        // ---- e-phase (fp16x2 MUFU): rows wid*16..+15; lane j=2L,2L+1 (+64) ----
        {
            float2 tAf = *(const float2*)&tgt_s[2 * lane];
            float2 tBf = *(const float2*)&tgt_s[64 + 2 * lane];
            const half2 tA2 = __floats2half2_rn(0.5f * tAf.x, 0.5f * tAf.y);
            const half2 tB2 = __floats2half2_rn(0.5f * tBf.x, 0.5f * tBf.y);
            const half2 c2  = __float2half2_rn(EXP_SIG_C);
            const int mw = lane >> 4;
            const int mb = 2 * (lane & 15);

            #pragma unroll 2
            for (int rr = 0; rr < 16; rr++) {
                const int i = wid * 16 + rr;
                const half2 si2 = __float2half2_rn(0.5f * src_s[i]);
                unsigned w0 = maskb[i * 4 + mw]     >> mb;
                unsigned w1 = maskb[i * 4 + 2 + mw] >> mb;
                uint32_t thA, thB, pAb, pBb;
                asm("tanh.approx.f16x2 %0, %1;" : "=r"(thA) : "r"(h2u(__hadd2(si2, tA2))));
                asm("tanh.approx.f16x2 %0, %1;" : "=r"(thB) : "r"(h2u(__hadd2(si2, tB2))));
                asm("ex2.approx.f16x2 %0, %1;"
                    : "=r"(pAb) : "r"(h2u(__hfma2(c2, u2h(thA), c2))));
                asm("ex2.approx.f16x2 %0, %1;"
                    : "=r"(pBb) : "r"(h2u(__hfma2(c2, u2h(thB), c2))));
                uint32_t mA = ((w0 & 1u) ? 0u : 0xFFFFu) | ((w0 & 2u) ? 0u : 0xFFFF0000u);
                uint32_t mB = ((w1 & 1u) ? 0u : 0xFFFFu) | ((w1 & 2u) ? 0u : 0xFFFF0000u);
                half2 pa = u2h(pAb & mA);
                half2 pb = u2h(pBb & mB);
                float2 sf = __half22float2(__hadd2(pa, pb));
                float rs = sf.x + sf.y;
                #pragma unroll
                for (int m = 16; m >= 1; m >>= 1)
                    rs += __shfl_xor_sync(0xffffffffu, rs, m);
                const half2 inv2 = __float2half2_rn(rcp_approx(rs));
                *(half2*)(attn_h + i * HTS + 2 * lane)      = __hmul2(pa, inv2);
                *(half2*)(attn_h + i * HTS + 64 + 2 * lane) = __hmul2(pb, inv2);
            }
        }
        __syncthreads();

        // ---- GEMM2 (32x32 warp tile): C += attn[rblk*32.., :] @ htt[chf*32.., :] ----
        {
            const uint32_t aA0 = att_s + 2 * ((rblk * 32 + lrow) * HTS + 8 * lhi);
            const uint32_t aB0 = htt_s + 2 * ((chf * 32 + lrow) * HTS + 8 * lhi);

            #pragma unroll
            for (int ks = 0; ks < 8; ks++) {
                const uint32_t koff = 2 * (16 * ks);
                uint32_t A[2][4], B[2][4];
                ldm_x4(A[0][0], A[0][1], A[0][2], A[0][3], aA0 + koff);
                ldm_x4(A[1][0], A[1][1], A[1][2], A[1][3],
                       aA0 + 2 * (16 * HTS) + koff);
                ldm_x4(B[0][0], B[0][1], B[0][2], B[0][3], aB0 + koff);
                ldm_x4(B[1][0], B[1][1], B[1][2], B[1][3],
                       aB0 + 2 * (16 * HTS) + koff);
                #pragma unroll
                for (int mt = 0; mt < 2; mt++) {
                    mma_f16(C[mt * 4 + 0], A[mt][0], A[mt][1], A[mt][2], A[mt][3],
                            B[0][0], B[0][2]);
                    mma_f16(C[mt * 4 + 1], A[mt][0], A[mt][1], A[mt][2], A[mt][3],
                            B[0][1], B[0][3]);
                    mma_f16(C[mt * 4 + 2], A[mt][0], A[mt][1], A[mt][2], A[mt][3],
                            B[1][0], B[1][2]);
                    mma_f16(C[mt * 4 + 3], A[mt][0], A[mt][1], A[mt][2], A[mt][3],
                            B[1][1], B[1][3]);
                }
            }
        }
        // loop-top __syncthreads() protects attn before next Wtk stage
    }

    // ---------------- Epilogue: x0.25 -> out (full: store; tail: red.add) -----
    #pragma unroll
    for (int mt = 0; mt < 2; mt++) {
        #pragma unroll
        for (int nt = 0; nt < 4; nt++) {
            const int ti  = mt * 4 + nt;
            const int row = rblk * 32 + mt * 16 + g;
            const int col = chf * 32 + nt * 8 + 2 * t;
            float v0 = C[ti][0] * 0.25f, v1 = C[ti][1] * 0.25f;
            float v2 = C[ti][2] * 0.25f, v3 = C[ti][3] * 0.25f;
            if (full) {
                float2 o0; o0.x = v0; o0.y = v1;
                float2 o1; o1.x = v2; o1.y = v3;
                *(float2*)&obase[row * 64 + col]       = o0;
                *(float2*)&obase[(row + 8) * 64 + col] = o1;
            } else {
                // two commutative adds onto zeroed memory -> deterministic
                red_add_f32(&obase[row * 64 + col],           v0);
                red_add_f32(&obase[row * 64 + col + 1],       v1);
                red_add_f32(&obase[(row + 8) * 64 + col],     v2);
                red_add_f32(&obase[(row + 8) * 64 + col + 1], v3);
            }
        }
    }
}

extern "C" void kernel_launch(void* const* d_in, const int* in_sizes, int n_in,
                              void* d_out, int out_size)
{
    const float* h   = (const float*)d_in[0];
    const float* adj = (const float*)d_in[1];
    const float* W   = (const float*)d_in[2];
    const float* a   = (const float*)d_in[3];
    float* out = (float*)d_out;

    static bool attr_set = false;
    if (!attr_set) {
        cudaFuncSetAttribute(gat_fused_kernel,
                             cudaFuncAttributeMaxDynamicSharedMemorySize,
                             SMEM_BYTES);
        attr_set = true;
    }

    // Zero the tail region (accumulated via red.global.add by tail CTAs).
    cudaMemsetAsync(out + (size_t)FULLC * 128 * 64, 0,
                    (size_t)TAILB * 128 * 64 * sizeof(float), 0);
    gat_fused_kernel<<<FULLC + 2 * TAILB, THREADS, SMEM_BYTES>>>(h, adj, W, a, out);
}

// round 17
// speedup vs baseline: 1.1237x; 1.1237x over previous
#include <cuda_runtime.h>
#include <cuda_fp16.h>
#include <cstdint>
#include <cstring>

// Problem constants
#define BATCH_SEQ 640          // B*S = 32*20
#define THREADS   256
#define ADJ_THR   0.05f
#define FULLC     456          // full-CTA count (= 152 SMs x 3 CTAs)
#define TAILB     (BATCH_SEQ - FULLC)   // 184 tail batch-seqs, 2 CTAs each

__device__ __forceinline__ float rcp_approx(float x) {
    float r; asm("rcp.approx.f32 %0, %1;" : "=f"(r) : "f"(x)); return r;
}
__device__ __forceinline__ uint32_t h2u(half2 v) { uint32_t r; memcpy(&r, &v, 4); return r; }
__device__ __forceinline__ half2 u2h(uint32_t v) { half2 r; memcpy(&r, &v, 4); return r; }
// exp(sigmoid(2*xh)) pairwise in fp16: 2^(c*tanh(xh)+c), c = log2(e)/2
#define EXP_SIG_C 0.72134752044f
__device__ __forceinline__ uint32_t expsig2(half2 x, half2 c2) {
    uint32_t th, r;
    asm("tanh.approx.f16x2 %0, %1;" : "=r"(th) : "r"(h2u(x)));
    asm("ex2.approx.f16x2 %0, %1;" : "=r"(r) : "r"(h2u(__hfma2(c2, u2h(th), c2))));
    return r;
}
// keep-mask from 2 mask bits (bit set == masked out)
__device__ __forceinline__ uint32_t msk2(unsigned bits) {
    return ((bits & 1u) ? 0u : 0xFFFFu) | ((bits & 2u) ? 0u : 0xFFFF0000u);
}
// fp16 mma m16n8k16, fp32 accum
__device__ __forceinline__ void mma_f16(float c[4],
                                        uint32_t a0, uint32_t a1, uint32_t a2, uint32_t a3,
                                        uint32_t b0, uint32_t b1) {
    asm volatile("mma.sync.aligned.m16n8k16.row.col.f32.f16.f16.f32 "
                 "{%0,%1,%2,%3}, {%4,%5,%6,%7}, {%8,%9}, {%0,%1,%2,%3};"
                 : "+f"(c[0]), "+f"(c[1]), "+f"(c[2]), "+f"(c[3])
                 : "r"(a0), "r"(a1), "r"(a2), "r"(a3), "r"(b0), "r"(b1));
}
__device__ __forceinline__ uint32_t cvta_s(const void* p) {
    uint32_t a; asm("{ .reg .u64 t; cvta.to.shared.u64 t, %1; cvt.u32.u64 %0, t; }"
                    : "=r"(a) : "l"(p));
    return a;
}
__device__ __forceinline__ void ldm_x4(uint32_t& r0, uint32_t& r1,
                                       uint32_t& r2, uint32_t& r3, uint32_t a) {
    asm volatile("ldmatrix.sync.aligned.m8n8.x4.shared.b16 {%0,%1,%2,%3}, [%4];"
                 : "=r"(r0), "=r"(r1), "=r"(r2), "=r"(r3) : "r"(a));
}
__device__ __forceinline__ void ldm_x4_t(uint32_t& r0, uint32_t& r1,
                                         uint32_t& r2, uint32_t& r3, uint32_t a) {
    asm volatile("ldmatrix.sync.aligned.m8n8.x4.trans.shared.b16 {%0,%1,%2,%3}, [%4];"
                 : "=r"(r0), "=r"(r1), "=r"(r2), "=r"(r3) : "r"(a));
}
__device__ __forceinline__ void red_add_f32(float* p, float v) {
    asm volatile("red.global.add.f32 [%0], %1;" :: "l"(p), "f"(v) : "memory");
}

// Shared memory layout (bytes) — ONE head resident at a time:
//   hs   [128 row][64 k] fp16 XOR-swz @ 0      (16384)
//   htt  [64 o][136 k-halves] fp16    @ 16384  (17408)  current head's ht^T
//   SCRATCH @ 33792 (34816):
//     GEMM1 phase : Wtk [64 k][64 o] fp16, o XOR-swz by k   (8192)
//     e/GEMM2     : fb  [8 warp][8 ks][4 reg][32 lane] u32  (32768)
//   src_s [128] f32  @ 68608 (512)
//   tgt_s [128] f32  @ 69120 (512)
//   maskb [512] u32  @ 69632 (2048)
//   a_s   [512] f32  @ 71680 (2048)
// total 73728 B -> 3 CTAs/SM
#define HTS       136
#define HTT_OFF   16384
#define ATT_OFF   33792
#define SRC_OFF   68608
#define TGT_OFF   69120
#define MSK_OFF   69632
#define AS_OFF    71680
#define SMEM_BYTES 73728

extern __shared__ char smem_b[];

__global__ __launch_bounds__(THREADS, 3)
void gat_fused_kernel(const float* __restrict__ hg,
                      const float* __restrict__ adjg,
                      const float* __restrict__ Wg,
                      const float* __restrict__ ag,
                      float* __restrict__ outg)
{
    __half* hs     = (__half*)smem_b;
    __half* htt    = (__half*)(smem_b + HTT_OFF);
    __half* Wtk    = (__half*)(smem_b + ATT_OFF);
    float*  src_s  = (float*)(smem_b + SRC_OFF);
    float*  tgt_s  = (float*)(smem_b + TGT_OFF);
    unsigned* maskb = (unsigned*)(smem_b + MSK_OFF);
    float*  a_s    = (float*)(smem_b + AS_OFF);

    const int tid  = threadIdx.x;
    const int lane = tid & 31;
    const int wid  = tid >> 5;      // 0..7
    const int g    = lane >> 2;     // 0..7
    const int t    = lane & 3;      // 0..3
    const int t2   = 2 * t;
    const int lrow = lane & 15;
    const int lhi  = lane >> 4;
    const int bid  = blockIdx.x;

    // ---- Mixed-grid decode: full CTA (4 heads) or tail CTA (head pair) ----
    int bs, h0, h1;
    bool full;
    if (bid < FULLC) {
        bs = bid; h0 = 0; h1 = 4; full = true;
    } else {
        int r  = bid - FULLC;
        bs = FULLC + (r >> 1);
        h0 = (r & 1) * 2; h1 = h0 + 2; full = false;
    }
    float* obase = outg + (size_t)bs * 128 * 64;

    const float* hb   = hg   + (size_t)bs * 128 * 64;
    const float* adjb = adjg + (size_t)bs * 128 * 128;

    const uint32_t hs_s  = cvta_s(hs);
    const uint32_t htt_s = cvta_s(htt);
    const uint32_t wtk_s = cvta_s(Wtk);
    uint32_t* fbu = (uint32_t*)(smem_b + ATT_OFF) + wid * 1024;

    // ---------------- Prologue: a_s, adjacency bitmask, hs (fp16 h) -----------
    a_s[tid]       = ag[tid];
    a_s[256 + tid] = ag[256 + tid];

    // adj mask via float4 + nibble shfl-OR tree (bit j%32 of word row*4 + j/32)
    {
        const int nsh = 4 * (lane & 7);
        #pragma unroll 4
        for (int it = 0; it < 16; it++) {
            const int row = it * 8 + wid;
            float4 v = *(const float4*)&adjb[row * 128 + 4 * lane];
            unsigned nib = (v.x < ADJ_THR ? 1u : 0u) | (v.y < ADJ_THR ? 2u : 0u)
                         | (v.z < ADJ_THR ? 4u : 0u) | (v.w < ADJ_THR ? 8u : 0u);
            unsigned word = nib << nsh;
            word |= __shfl_xor_sync(0xffffffffu, word, 1);
            word |= __shfl_xor_sync(0xffffffffu, word, 2);
            word |= __shfl_xor_sync(0xffffffffu, word, 4);
            if ((lane & 7) == 0) maskb[row * 4 + (lane >> 3)] = word;
        }
    }

    // hs[row][k ^ 8*(row&7)] fp16
    #pragma unroll
    for (int it = 0; it < 8; it++) {
        int idx = it * 256 + tid;
        int row = idx >> 4;
        int k4  = (idx & 15) * 4;
        float4 v = *(const float4*)&hb[row * 64 + k4];
        __half* p = hs + row * 64 + (k4 ^ (8 * (row & 7)));
        *(half2*)p       = __floats2half2_rn(v.x, v.y);
        *(half2*)(p + 2) = __floats2half2_rn(v.z, v.w);
    }

    // GEMM2 accumulator: warp = rows wid*16 + {g, g+8}, all 64 cols, all heads
    float C[8][4];
    #pragma unroll
    for (int i = 0; i < 8; i++)
        #pragma unroll
        for (int q = 0; q < 4; q++) C[i][q] = 0.f;

    // ================== Per-head pipeline ==================
    #pragma unroll 1
    for (int h = h0; h < h1; h++) {
        __syncthreads();   // prev GEMM2 fb reads done (or prologue done)

        // ---- Stage Wtk[k][o ^ 8*(k&7)] = W[k][h*64+o] fp16 ----
        #pragma unroll
        for (int it = 0; it < 4; it++) {
            int idx = it * 256 + tid;
            int k   = idx >> 4;
            int o4  = (idx & 15) * 4;
            float4 v = *(const float4*)&Wg[k * 256 + h * 64 + o4];
            int base = k * 64 + (o4 ^ (8 * (k & 7)));
            *(half2*)&Wtk[base]     = __floats2half2_rn(v.x, v.y);
            *(half2*)&Wtk[base + 2] = __floats2half2_rn(v.z, v.w);
        }
        __syncthreads();

        // ---- GEMM1: htt[o][row] = W_h^T @ h^T ; warp tile 16 o x 64 rows ----
        {
            const int ob = (wid >> 1) * 16;   // o block
            const int rb = wid & 1;           // row half (64 rows)
            const int krow = (lane & 7) + 8 * lhi;            // 0..15
            const int och  = ob + 8 * ((lane >> 3) & 1);
            const uint32_t aA_base =
                wtk_s + 2 * (krow * 64 + (och ^ (8 * (krow & 7))));
            const uint32_t aB0 = hs_s + 2 * ((rb * 64 + lrow) * 64);

            #pragma unroll
            for (int qh = 0; qh < 2; qh++) {
                float D[4][4];
                #pragma unroll
                for (int i = 0; i < 4; i++)
                    #pragma unroll
                    for (int q = 0; q < 4; q++) D[i][q] = 0.f;

                #pragma unroll
                for (int ks = 0; ks < 4; ks++) {
                    uint32_t A0, A1, A2, A3;
                    ldm_x4_t(A0, A1, A2, A3, aA_base + ks * 2048);
                    const int chunk = ((ks * 16 + 8 * lhi) ^ (8 * (lrow & 7))) * 2;
                    #pragma unroll
                    for (int q2 = 0; q2 < 2; q2++) {
                        const int q = qh * 2 + q2;
                        uint32_t r0, r1, r2, r3;
                        ldm_x4(r0, r1, r2, r3, aB0 + 2 * (q * 16 * 64) + chunk);
                        mma_f16(D[2 * q2],     A0, A1, A2, A3, r0, r2);
                        mma_f16(D[2 * q2 + 1], A0, A1, A2, A3, r1, r3);
                    }
                }
                // store htt (half2, conflict-free)
                #pragma unroll
                for (int q2 = 0; q2 < 2; q2++) {
                    #pragma unroll
                    for (int j = 0; j < 2; j++) {
                        const float* c = D[2 * q2 + j];
                        const int row = rb * 64 + (qh * 2 + q2) * 16 + j * 8 + t2;
                        *(half2*)&htt[(ob + g) * HTS + row] =
                            __floats2half2_rn(c[0], c[1]);
                        *(half2*)&htt[(ob + g + 8) * HTS + row] =
                            __floats2half2_rn(c[2], c[3]);
                    }
                }
            }
        }
        __syncthreads();   // htt visible; Wtk reads done -> fb region free

        // ---- src/tgt: exact fp32 dots over htt columns (conflict-free) ----
        {
            const int ol = lane & 7;
            const int rp = lane >> 3;
            #pragma unroll
            for (int pass = 0; pass < 2; pass++) {
                const int row = wid * 16 + 2 * (rp + 4 * pass);
                float s0 = 0.f, s1 = 0.f, t0 = 0.f, t1 = 0.f;
                #pragma unroll
                for (int oo = 0; oo < 8; oo++) {
                    const int o = oo * 8 + ol;
                    float2 f = __half22float2(*(const half2*)&htt[o * HTS + row]);
                    float av = a_s[h * 128 + o];
                    float bv = a_s[h * 128 + 64 + o];
                    s0 = fmaf(f.x, av, s0); s1 = fmaf(f.y, av, s1);
                    t0 = fmaf(f.x, bv, t0); t1 = fmaf(f.y, bv, t1);
                }
                #pragma unroll
                for (int m = 1; m <= 4; m <<= 1) {
                    s0 += __shfl_xor_sync(0xffffffffu, s0, m);
                    s1 += __shfl_xor_sync(0xffffffffu, s1, m);
                    t0 += __shfl_xor_sync(0xffffffffu, t0, m);
                    t1 += __shfl_xor_sync(0xffffffffu, t1, m);
                }
                if (ol == 0) {
                    float2 sv; sv.x = s0; sv.y = s1;
                    float2 tv; tv.x = t0; tv.y = t1;
                    *(float2*)&src_s[row] = sv;
                    *(float2*)&tgt_s[row] = tv;
                }
            }
        }
        __syncthreads();   // src/tgt visible (cross-warp tgt reads next)

        // ---- e-phase (fragment-direct) + rowsum MMA + GEMM2: warp-local ----
        {
            const half2 c2 = __float2half2_rn(EXP_SIG_C);
            const uint32_t one2 = 0x3C003C00u;   // half2(1.0, 1.0)
            const half2 si2g  = __float2half2_rn(0.5f * src_s[wid * 16 + g]);
            const half2 si2g8 = __float2half2_rn(0.5f * src_s[wid * 16 + g + 8]);
            unsigned mg_[4], mg8_[4];
            #pragma unroll
            for (int w = 0; w < 4; w++) {
                mg_[w]  = maskb[(wid * 16 + g) * 4 + w];
                mg8_[w] = maskb[(wid * 16 + g + 8) * 4 + w];
            }

            float R[4] = {0.f, 0.f, 0.f, 0.f};
            #pragma unroll
            for (int ks = 0; ks < 8; ks++) {
                float2 tlo = *(const float2*)&tgt_s[16 * ks + t2];
                float2 thi = *(const float2*)&tgt_s[16 * ks + 8 + t2];
                half2 th_lo = __floats2half2_rn(0.5f * tlo.x, 0.5f * tlo.y);
                half2 th_hi = __floats2half2_rn(0.5f * thi.x, 0.5f * thi.y);
                const int bplo = (ks & 1) * 16 + t2;
                unsigned wg_  = mg_[ks >> 1]  >> bplo;
                unsigned wg8_ = mg8_[ks >> 1] >> bplo;
                uint32_t a0 = expsig2(__hadd2(si2g,  th_lo), c2) & msk2(wg_);
                uint32_t a1 = expsig2(__hadd2(si2g8, th_lo), c2) & msk2(wg8_);
                uint32_t a2 = expsig2(__hadd2(si2g,  th_hi), c2) & msk2(wg_ >> 8);
                uint32_t a3 = expsig2(__hadd2(si2g8, th_hi), c2) & msk2(wg8_ >> 8);
                fbu[(ks * 4 + 0) * 32 + lane] = a0;
                fbu[(ks * 4 + 1) * 32 + lane] = a1;
                fbu[(ks * 4 + 2) * 32 + lane] = a2;
                fbu[(ks * 4 + 3) * 32 + lane] = a3;
                mma_f16(R, a0, a1, a2, a3, one2, one2);   // rowsum
            }
            // R[0] = rowsum(row g), R[2] = rowsum(row g+8) — per-lane, no shfl
            const half2 invg2  = __float2half2_rn(rcp_approx(R[0]));
            const half2 invg82 = __float2half2_rn(rcp_approx(R[2]));

            // GEMM2: A from fb (scaled on reload), B = htt (all 64 o)
            const uint32_t aB0 = htt_s + 2 * (lrow * HTS + 8 * lhi);
            #pragma unroll
            for (int ks = 0; ks < 8; ks++) {
                uint32_t a0 = h2u(__hmul2(u2h(fbu[(ks * 4 + 0) * 32 + lane]), invg2));
                uint32_t a1 = h2u(__hmul2(u2h(fbu[(ks * 4 + 1) * 32 + lane]), invg82));
                uint32_t a2 = h2u(__hmul2(u2h(fbu[(ks * 4 + 2) * 32 + lane]), invg2));
                uint32_t a3 = h2u(__hmul2(u2h(fbu[(ks * 4 + 3) * 32 + lane]), invg82));
                const uint32_t koff = 2 * (16 * ks);
                #pragma unroll
                for (int q = 0; q < 4; q++) {
                    uint32_t b0, b1, b2, b3;
                    ldm_x4(b0, b1, b2, b3, aB0 + 2 * (q * 16 * HTS) + koff);
                    mma_f16(C[2 * q],     a0, a1, a2, a3, b0, b2);
                    mma_f16(C[2 * q + 1], a0, a1, a2, a3, b1, b3);
                }
            }
        }
        // loop-top __syncthreads() protects Wtk/fb before next head
    }

    // ---------------- Epilogue: rows wid*16+{g,g+8}; x0.25 --------------------
    #pragma unroll
    for (int q = 0; q < 4; q++) {
        #pragma unroll
        for (int j = 0; j < 2; j++) {
            const int ti  = 2 * q + j;
            const int row = wid * 16 + g;
            const int col = q * 16 + j * 8 + t2;
            float v0 = C[ti][0] * 0.25f, v1 = C[ti][1] * 0.25f;
            float v2 = C[ti][2] * 0.25f, v3 = C[ti][3] * 0.25f;
            if (full) {
                float2 o0; o0.x = v0; o0.y = v1;
                float2 o1; o1.x = v2; o1.y = v3;
                *(float2*)&obase[row * 64 + col]       = o0;
                *(float2*)&obase[(row + 8) * 64 + col] = o1;
            } else {
                red_add_f32(&obase[row * 64 + col],           v0);
                red_add_f32(&obase[row * 64 + col + 1],       v1);
                red_add_f32(&obase[(row + 8) * 64 + col],     v2);
                red_add_f32(&obase[(row + 8) * 64 + col + 1], v3);
            }
        }
    }
}

extern "C" void kernel_launch(void* const* d_in, const int* in_sizes, int n_in,
                              void* d_out, int out_size)
{
    const float* h   = (const float*)d_in[0];
    const float* adj = (const float*)d_in[1];
    const float* W   = (const float*)d_in[2];
    const float* a   = (const float*)d_in[3];
    float* out = (float*)d_out;

    static bool attr_set = false;
    if (!attr_set) {
        cudaFuncSetAttribute(gat_fused_kernel,
                             cudaFuncAttributeMaxDynamicSharedMemorySize,
                             SMEM_BYTES);
        attr_set = true;
    }

    // Zero the tail region (accumulated via red.global.add by tail CTAs).
    cudaMemsetAsync(out + (size_t)FULLC * 128 * 64, 0,
                    (size_t)TAILB * 128 * 64 * sizeof(float), 0);
    gat_fused_kernel<<<FULLC + 2 * TAILB, THREADS, SMEM_BYTES>>>(h, adj, W, a, out);
}